// round 6
// baseline (speedup 1.0000x reference)
#include <cuda_runtime.h>
#include <cstdint>

typedef unsigned long long ull;

#define NEXP     16
#define DIM      256     // K
#define PP       64      // N
#define TCHUNK   2048
#define MT       128     // M tile
#define KC       32      // K chunk
#define XS2      68      // x_s2 row stride in floats (row holds 2*KC=64) -> 272B, conflict-free
#define NTHREADS 256

// ---- packed f32x2 (FFMA2) helpers ----
__device__ __forceinline__ void ffma2(ull& d, ull a, ull b) {
    asm("fma.rn.f32x2 %0, %1, %2, %0;" : "+l"(d) : "l"(a), "l"(b));
}
__device__ __forceinline__ float2 unpack2(ull v) {
    float2 r;
    asm("mov.b64 {%0, %1}, %2;" : "=f"(r.x), "=f"(r.y) : "l"(v));
    return r;
}

// Inner loop over one K-chunk. x_s2 rows hold duplicated pairs {v,v} so an
// LDS.128 yields two packed FFMA2 multiplicands with zero pack instructions.
// b_chunk must already include the thread's tn8 column offset.
template <int NG>
__device__ __forceinline__ void fma_chunk(ull (&acc)[4][4],
                                          const float* __restrict__ x_s2,
                                          const float* __restrict__ b_chunk,
                                          int mb) {
    #pragma unroll
    for (int k2 = 0; k2 < KC / 2; k2++) {           // two k per iteration
        ulonglong2 xa[NG];
        #pragma unroll
        for (int i = 0; i < NG; i++)
            xa[i] = *(const ulonglong2*)(x_s2 + (mb + 32 * i) * XS2 + k2 * 4);
        #pragma unroll
        for (int kk = 0; kk < 2; kk++) {
            const float* brow = b_chunk + (k2 * 2 + kk) * PP;
            ulonglong2 bA = *(const ulonglong2*)(brow);      // n {0,1},{2,3}
            ulonglong2 bB = *(const ulonglong2*)(brow + 4);  // n {4,5},{6,7}
            #pragma unroll
            for (int i = 0; i < NG; i++) {
                ull aa = kk ? xa[i].y : xa[i].x;   // register pair, no MOV
                ffma2(acc[i][0], aa, bA.x);
                ffma2(acc[i][1], aa, bA.y);
                ffma2(acc[i][2], aa, bB.x);
                ffma2(acc[i][3], aa, bB.y);
            }
        }
    }
}

extern __shared__ char smem_raw[];

__global__ __launch_bounds__(NTHREADS, 2)
void moe_pixels_kernel(const float* __restrict__ x,
                       const float* __restrict__ W,
                       const float* __restrict__ bias,
                       const int*   __restrict__ bidx,
                       float*       __restrict__ out,
                       int n_tokens)
{
    float* b_s    = (float*)smem_raw;              // [DIM][PP] f32   = 65536 B
    float* x_s2   = b_s + DIM * PP;                // [MT][XS2] f32   = 34816 B
    int*   s_rows = (int*)(x_s2 + MT * XS2);       // [TCHUNK]        =  8192 B
    float* bias_s = (float*)(s_rows + TCHUNK);     // [PP]            =   256 B
    __shared__ int s_cnt;

    const int tid  = threadIdx.x;
    const int e    = blockIdx.y;
    const int base = blockIdx.x * TCHUNK;

    if (tid == 0) s_cnt = 0;
    __syncthreads();

    // ---- Phase 1: select tokens routed to expert e in this chunk ----
    int lim = n_tokens - base;
    if (lim > TCHUNK) lim = TCHUNK;
    for (int i = tid; i < lim; i += NTHREADS) {
        if (bidx[base + i] == e) {
            int pos = atomicAdd(&s_cnt, 1);
            s_rows[pos] = base + i;
        }
    }

    // ---- Phase 2: stage W[e] (already [K][N] row-major) + bias ----
    {
        const float4* src = (const float4*)(W + (size_t)e * DIM * PP);
        float4* dst = (float4*)b_s;
        #pragma unroll
        for (int i = 0; i < (DIM * PP / 4) / NTHREADS; i++)      // 16 iters
            dst[tid + i * NTHREADS] = src[tid + i * NTHREADS];
    }
    if (tid < PP) bias_s[tid] = bias[e * PP + tid];
    __syncthreads();

    const int cnt = s_cnt;
    if (cnt == 0) return;

    // Thread tile: 4 m (strided by 32) x 8 n (contiguous)
    const int mb  = tid >> 3;          // 0..31
    const int tn8 = (tid & 7) * 8;     // 0..56

    const float4 bv0 = *(const float4*)(bias_s + tn8);
    const float4 bv1 = *(const float4*)(bias_s + tn8 + 4);

    // x staging map: 2 threads per row; each covers 16 floats (4 x float4)
    const int st_r    = tid >> 1;            // row 0..127
    const int st_koff = (tid & 1) * 16;      // k offset within chunk

    for (int m0 = 0; m0 < cnt; m0 += MT) {
        int mcount = cnt - m0;
        if (mcount > MT) mcount = MT;
        const int  ngrp   = (mcount + 31) >> 5;
        const bool rvalid = st_r < mcount;
        const size_t gxrow = rvalid ? (size_t)s_rows[m0 + st_r] * DIM : 0;

        ull acc[4][4];
        #pragma unroll
        for (int i = 0; i < 4; i++)
            #pragma unroll
            for (int j = 0; j < 4; j++) acc[i][j] = 0ULL;

        // prefetch chunk 0
        float4 pf[4];
        if (rvalid) {
            #pragma unroll
            for (int j = 0; j < 4; j++)
                pf[j] = *(const float4*)(x + gxrow + st_koff + j * 4);
        }

        for (int c = 0; c < DIM / KC; c++) {
            __syncthreads();   // previous chunk's readers done
            if (rvalid) {
                float* drow = x_s2 + st_r * XS2 + st_koff * 2;
                #pragma unroll
                for (int j = 0; j < 4; j++) {
                    float4 v = pf[j];
                    *(float4*)(drow + j * 8)     = make_float4(v.x, v.x, v.y, v.y);
                    *(float4*)(drow + j * 8 + 4) = make_float4(v.z, v.z, v.w, v.w);
                }
            }
            __syncthreads();
            if (c + 1 < DIM / KC && rvalid) {
                const float* gsrc = x + gxrow + (c + 1) * KC + st_koff;
                #pragma unroll
                for (int j = 0; j < 4; j++)
                    pf[j] = *(const float4*)(gsrc + j * 4);
            }

            // NOTE: tn8 folded in (this was the R5 bug)
            const float* b_chunk = b_s + c * KC * PP + tn8;
            switch (ngrp) {
                case 1:  fma_chunk<1>(acc, x_s2, b_chunk, mb); break;
                case 2:  fma_chunk<2>(acc, x_s2, b_chunk, mb); break;
                case 3:  fma_chunk<3>(acc, x_s2, b_chunk, mb); break;
                default: fma_chunk<4>(acc, x_s2, b_chunk, mb); break;
            }
        }

        // ---- Epilogue: bias + scattered row writes ----
        #pragma unroll
        for (int i = 0; i < 4; i++) {
            int m = mb + 32 * i;
            if (m < mcount) {
                float* o = out + (size_t)s_rows[m0 + m] * PP + tn8;
                float2 p0 = unpack2(acc[i][0]);
                float2 p1 = unpack2(acc[i][1]);
                float2 p2 = unpack2(acc[i][2]);
                float2 p3 = unpack2(acc[i][3]);
                float4 r0 = make_float4(p0.x + bv0.x, p0.y + bv0.y,
                                        p1.x + bv0.z, p1.y + bv0.w);
                float4 r1 = make_float4(p2.x + bv1.x, p2.y + bv1.y,
                                        p3.x + bv1.z, p3.y + bv1.w);
                *(float4*)(o)     = r0;
                *(float4*)(o + 4) = r1;
            }
        }
    }
}

extern "C" void kernel_launch(void* const* d_in, const int* in_sizes, int n_in,
                              void* d_out, int out_size) {
    const float* x    = (const float*)d_in[0];
    const float* W    = (const float*)d_in[1];
    const float* bias = (const float*)d_in[2];
    const int*   idx  = (const int*)d_in[3];
    float*       out  = (float*)d_out;

    const int n_tokens = in_sizes[3];

    const int smem_bytes = (DIM * PP + MT * XS2 + PP) * 4 + TCHUNK * 4;  // 108,800 B
    cudaFuncSetAttribute(moe_pixels_kernel,
                         cudaFuncAttributeMaxDynamicSharedMemorySize, smem_bytes);

    dim3 grid((n_tokens + TCHUNK - 1) / TCHUNK, NEXP);
    moe_pixels_kernel<<<grid, NTHREADS, smem_bytes>>>(x, W, bias, idx, out, n_tokens);
}

// round 7
// speedup vs baseline: 1.5474x; 1.5474x over previous
#include <cuda_runtime.h>
#include <cstdint>

#define NEXP     16
#define DIM      256     // K
#define PP       64      // N
#define TCHUNK   2048
#define MT       128     // M tile rows
#define NTHREADS 256

// dynamic smem layout (bytes)
#define SM_AH    0        // [128][256] bf16 swizzled  = 65536
#define SM_AL    65536    // 65536
#define SM_BH    131072   // [64][256]  bf16 swizzled  = 32768
#define SM_BL    163840   // 32768
#define SM_ROWS  196608   // TCHUNK * 4 = 8192
#define SM_BIAS  204800   // 64 * 4
#define SMEM_DYN 205056
// transient f32 scratch for W transpose: [256][68] = 69632 B, overlaps AH/AL
#define WS_PAD   68

__device__ __forceinline__ uint32_t smem_u32(const void* p) {
    uint32_t a;
    asm("{ .reg .u64 t; cvta.to.shared.u64 t, %1; cvt.u32.u64 %0, t; }" : "=r"(a) : "l"(p));
    return a;
}

// Swizzled tile layout: row-major [r][k] bf16, row stride 512B, 16B chunks
// XOR-permuted within each 128B group so ldmatrix (8 rows, same k-chunk) is
// conflict-free: chunk' = (ch & ~7) | ((ch ^ r) & 7).
__device__ __forceinline__ uint32_t tile_off(uint32_t r, uint32_t k) {
    uint32_t ch  = k >> 3;
    uint32_t chs = (ch & 24u) | ((ch ^ r) & 7u);
    return r * 512u + chs * 16u + (k & 7u) * 2u;
}

__device__ __forceinline__ void ldmx4(uint32_t (&r)[4], uint32_t a) {
    asm volatile("ldmatrix.sync.aligned.m8n8.x4.shared.b16 {%0,%1,%2,%3}, [%4];"
                 : "=r"(r[0]), "=r"(r[1]), "=r"(r[2]), "=r"(r[3]) : "r"(a));
}

__device__ __forceinline__ void mma16816(float (&d)[4], const uint32_t (&a)[4],
                                         uint32_t b0, uint32_t b1) {
    asm volatile("mma.sync.aligned.m16n8k16.row.col.f32.bf16.bf16.f32 "
                 "{%0,%1,%2,%3}, {%4,%5,%6,%7}, {%8,%9}, {%0,%1,%2,%3};"
                 : "+f"(d[0]), "+f"(d[1]), "+f"(d[2]), "+f"(d[3])
                 : "r"(a[0]), "r"(a[1]), "r"(a[2]), "r"(a[3]), "r"(b0), "r"(b1));
}

// pack {elem k+1, elem k} -> bf16x2 (low half = first/even element)
__device__ __forceinline__ uint32_t bf16x2(float hi_e, float lo_e) {
    uint32_t r;
    asm("cvt.rn.bf16x2.f32 %0, %1, %2;" : "=r"(r) : "f"(hi_e), "f"(lo_e));
    return r;
}

// split 8 consecutive f32 into hi (truncated bf16) and lo (rounded residual)
__device__ __forceinline__ void split8(const float4 v0, const float4 v1,
                                       uint4& hi, uint4& lo) {
    uint32_t u0=__float_as_uint(v0.x), u1=__float_as_uint(v0.y);
    uint32_t u2=__float_as_uint(v0.z), u3=__float_as_uint(v0.w);
    uint32_t u4=__float_as_uint(v1.x), u5=__float_as_uint(v1.y);
    uint32_t u6=__float_as_uint(v1.z), u7=__float_as_uint(v1.w);
    hi.x=(u0>>16)|(u1&0xFFFF0000u); hi.y=(u2>>16)|(u3&0xFFFF0000u);
    hi.z=(u4>>16)|(u5&0xFFFF0000u); hi.w=(u6>>16)|(u7&0xFFFF0000u);
    lo.x=bf16x2(v0.y-__uint_as_float(u1&0xFFFF0000u), v0.x-__uint_as_float(u0&0xFFFF0000u));
    lo.y=bf16x2(v0.w-__uint_as_float(u3&0xFFFF0000u), v0.z-__uint_as_float(u2&0xFFFF0000u));
    lo.z=bf16x2(v1.y-__uint_as_float(u5&0xFFFF0000u), v1.x-__uint_as_float(u4&0xFFFF0000u));
    lo.w=bf16x2(v1.w-__uint_as_float(u7&0xFFFF0000u), v1.z-__uint_as_float(u6&0xFFFF0000u));
}

extern __shared__ char smem_raw[];

__global__ __launch_bounds__(NTHREADS, 1)
void moe_mma_kernel(const float* __restrict__ x,
                    const float* __restrict__ W,
                    const float* __restrict__ bias,
                    const int*   __restrict__ bidx,
                    float*       __restrict__ out,
                    int n_tokens)
{
    __shared__ int s_cnt;

    char* smem = smem_raw;
    const uint32_t sb = smem_u32(smem);

    const int tid  = threadIdx.x;
    const int wid  = tid >> 5;
    const int lane = tid & 31;
    const int e    = blockIdx.y;
    const int base = blockIdx.x * TCHUNK;

    int*   s_rows = (int*)(smem + SM_ROWS);
    float* bias_s = (float*)(smem + SM_BIAS);
    float* w_s    = (float*)smem;                 // transient scratch

    if (tid == 0) s_cnt = 0;
    __syncthreads();

    // ---- Phase 1: select tokens for expert e; stage W[e] f32 into scratch ----
    int lim = n_tokens - base;
    if (lim > TCHUNK) lim = TCHUNK;
    for (int i = tid; i < lim; i += NTHREADS) {
        if (bidx[base + i] == e) {
            int pos = atomicAdd(&s_cnt, 1);
            s_rows[pos] = base + i;
        }
    }
    {
        const float4* src = (const float4*)(W + (size_t)e * DIM * PP);
        #pragma unroll
        for (int p = 0; p < (DIM * PP / 4) / NTHREADS; p++) {   // 16 passes
            int idx = p * NTHREADS + tid;                       // float4 index
            int k   = idx >> 4;
            int n4  = (idx & 15) * 4;
            *(float4*)(w_s + k * WS_PAD + n4) = src[idx];
        }
    }
    if (tid < PP) bias_s[tid] = bias[e * PP + tid];
    __syncthreads();

    const int cnt = s_cnt;
    if (cnt == 0) return;

    // ---- Phase 2: build B^T hi/lo [n][k] bf16 swizzled from scratch ----
    {
        const int n  = tid >> 2;            // 0..63
        const int ks = (tid & 3) * 64;      // k segment base
        #pragma unroll
        for (int c = 0; c < 8; c++) {
            int kb = ks + c * 8;
            float a0 = w_s[(kb+0)*WS_PAD + n], a1 = w_s[(kb+1)*WS_PAD + n];
            float a2 = w_s[(kb+2)*WS_PAD + n], a3 = w_s[(kb+3)*WS_PAD + n];
            float a4 = w_s[(kb+4)*WS_PAD + n], a5 = w_s[(kb+5)*WS_PAD + n];
            float a6 = w_s[(kb+6)*WS_PAD + n], a7 = w_s[(kb+7)*WS_PAD + n];
            uint4 hi, lo;
            split8(make_float4(a0,a1,a2,a3), make_float4(a4,a5,a6,a7), hi, lo);
            uint32_t so = tile_off((uint32_t)n, (uint32_t)kb);
            *(uint4*)(smem + SM_BH + so) = hi;
            *(uint4*)(smem + SM_BL + so) = lo;
        }
    }
    __syncthreads();   // B ready; scratch (AH/AL region) now reusable

    // warp tiling: 4m x 2n warps, warp tile 32m x 32n
    const int wm = wid >> 1, wn = wid & 1;
    const int m_base = wm * 32, n_base = wn * 32;

    // per-lane geometry
    const int aRow = (lane & 7) + ((lane >> 3) & 1) * 8;   // row within 16
    const int aKof = (lane >> 4) * 8;                      // k offset 0/8
    const uint32_t rowA0 = (uint32_t)(m_base + aRow);      // mi=0 row
    const uint32_t rowB  = (uint32_t)(n_base + lane);      // b row (n)

    // bias per lane per n-frag
    float2 bc[4];
    #pragma unroll
    for (int nj = 0; nj < 4; nj++)
        bc[nj] = *(const float2*)(bias_s + n_base + nj * 8 + (lane & 3) * 2);

    // A staging map: thread -> (row, k-half)
    const int st_m  = tid >> 1;
    const int st_kh = (tid & 1) * 128;

    for (int m0 = 0; m0 < cnt; m0 += MT) {
        int mcount = cnt - m0;
        if (mcount > MT) mcount = MT;

        // ---- stage A hi/lo (gather + split) ----
        if (st_m < mcount) {
            const float* xr = x + (size_t)s_rows[m0 + st_m] * DIM + st_kh;
            #pragma unroll
            for (int c = 0; c < 16; c++) {
                int kb = c * 8;
                float4 v0 = *(const float4*)(xr + kb);
                float4 v1 = *(const float4*)(xr + kb + 4);
                uint4 hi, lo;
                split8(v0, v1, hi, lo);
                uint32_t so = tile_off((uint32_t)st_m, (uint32_t)(st_kh + kb));
                *(uint4*)(smem + SM_AH + so) = hi;
                *(uint4*)(smem + SM_AL + so) = lo;
            }
        }
        __syncthreads();

        // ---- mainloop: 16 k-steps x (AH*BH + AL*BH + AH*BL) ----
        float acc[2][4][4];
        #pragma unroll
        for (int i = 0; i < 2; i++)
            #pragma unroll
            for (int j = 0; j < 4; j++)
                #pragma unroll
                for (int q = 0; q < 4; q++) acc[i][j][q] = 0.f;

        #pragma unroll 4
        for (int ks = 0; ks < 16; ks++) {
            const uint32_t kk = (uint32_t)(ks * 16);
            uint32_t aoff = tile_off(rowA0, kk + (uint32_t)aKof);
            uint32_t boff0 = tile_off(rowB, kk);
            uint32_t boff1 = tile_off(rowB, kk + 8);

            uint32_t AH0[4], AH1[4], AL0[4], AL1[4];
            ldmx4(AH0, sb + SM_AH + aoff);
            ldmx4(AH1, sb + SM_AH + aoff + 16 * 512);   // rows +16: same swizzle
            ldmx4(AL0, sb + SM_AL + aoff);
            ldmx4(AL1, sb + SM_AL + aoff + 16 * 512);

            uint32_t BH0[4], BH1[4], BL0[4], BL1[4];
            ldmx4(BH0, sb + SM_BH + boff0);
            ldmx4(BH1, sb + SM_BH + boff1);
            ldmx4(BL0, sb + SM_BL + boff0);
            ldmx4(BL1, sb + SM_BL + boff1);

            #pragma unroll
            for (int nj = 0; nj < 4; nj++) {
                mma16816(acc[0][nj], AH0, BH0[nj], BH1[nj]);
                mma16816(acc[1][nj], AH1, BH0[nj], BH1[nj]);
                mma16816(acc[0][nj], AL0, BH0[nj], BH1[nj]);
                mma16816(acc[1][nj], AL1, BH0[nj], BH1[nj]);
                mma16816(acc[0][nj], AH0, BL0[nj], BL1[nj]);
                mma16816(acc[1][nj], AH1, BL0[nj], BL1[nj]);
            }
        }

        // ---- epilogue: bias + scattered stores ----
        #pragma unroll
        for (int mi = 0; mi < 2; mi++) {
            int r0 = m_base + mi * 16 + (lane >> 2);
            int r1 = r0 + 8;
            #pragma unroll
            for (int nj = 0; nj < 4; nj++) {
                int c = n_base + nj * 8 + (lane & 3) * 2;
                if (r0 < mcount) {
                    float* o = out + (size_t)s_rows[m0 + r0] * PP + c;
                    o[0] = acc[mi][nj][0] + bc[nj].x;
                    o[1] = acc[mi][nj][1] + bc[nj].y;
                }
                if (r1 < mcount) {
                    float* o = out + (size_t)s_rows[m0 + r1] * PP + c;
                    o[0] = acc[mi][nj][2] + bc[nj].x;
                    o[1] = acc[mi][nj][3] + bc[nj].y;
                }
            }
        }
        __syncthreads();   // all mma/ldmatrix done before next A staging
    }
}

extern "C" void kernel_launch(void* const* d_in, const int* in_sizes, int n_in,
                              void* d_out, int out_size) {
    const float* x    = (const float*)d_in[0];
    const float* W    = (const float*)d_in[1];
    const float* bias = (const float*)d_in[2];
    const int*   idx  = (const int*)d_in[3];
    float*       out  = (float*)d_out;

    const int n_tokens = in_sizes[3];

    cudaFuncSetAttribute(moe_mma_kernel,
                         cudaFuncAttributeMaxDynamicSharedMemorySize, SMEM_DYN);

    dim3 grid((n_tokens + TCHUNK - 1) / TCHUNK, NEXP);
    moe_mma_kernel<<<grid, NTHREADS, SMEM_DYN>>>(x, W, bias, idx, out, n_tokens);
}

// round 9
// speedup vs baseline: 1.5956x; 1.0312x over previous
#include <cuda_runtime.h>
#include <cuda_bf16.h>
#include <cstdint>

#define NEXP     16
#define DIM      256     // K
#define PP       64      // N
#define TCHUNK   2048
#define MT       64      // M tile rows
#define NTHREADS 256

// smem: AH [64][256]bf16 swizzled (32KB) | AL (32KB) | rows (8KB)
#define SM_AH    0
#define SM_AL    32768
#define SM_ROWS  65536
#define SMEM_DYN 73728

// prepped weights: [E][N][K] bf16, hi = truncated top-16, lo = rounded residual
__device__ __nv_bfloat16 g_Wh[NEXP * PP * DIM];
__device__ __nv_bfloat16 g_Wl[NEXP * PP * DIM];

__device__ __forceinline__ uint32_t smem_u32(const void* p) {
    uint32_t a;
    asm("{ .reg .u64 t; cvta.to.shared.u64 t, %1; cvt.u32.u64 %0, t; }" : "=r"(a) : "l"(p));
    return a;
}

// Swizzled A tile: row-major [m][k] bf16, row stride 512B; 16B chunks XOR-permuted
// within each 128B group -> ldmatrix (8 rows, same k-chunk) conflict-free.
__device__ __forceinline__ uint32_t tile_off(uint32_t r, uint32_t k) {
    uint32_t ch  = k >> 3;
    uint32_t chs = (ch & 24u) | ((ch ^ r) & 7u);
    return r * 512u + chs * 16u + (k & 7u) * 2u;
}

__device__ __forceinline__ void ldmx4(uint32_t (&r)[4], uint32_t a) {
    asm volatile("ldmatrix.sync.aligned.m8n8.x4.shared.b16 {%0,%1,%2,%3}, [%4];"
                 : "=r"(r[0]), "=r"(r[1]), "=r"(r[2]), "=r"(r[3]) : "r"(a));
}

__device__ __forceinline__ void mma16816(float (&d)[4], const uint32_t (&a)[4],
                                         uint32_t b0, uint32_t b1) {
    asm volatile("mma.sync.aligned.m16n8k16.row.col.f32.bf16.bf16.f32 "
                 "{%0,%1,%2,%3}, {%4,%5,%6,%7}, {%8,%9}, {%0,%1,%2,%3};"
                 : "+f"(d[0]), "+f"(d[1]), "+f"(d[2]), "+f"(d[3])
                 : "r"(a[0]), "r"(a[1]), "r"(a[2]), "r"(a[3]), "r"(b0), "r"(b1));
}

__device__ __forceinline__ uint32_t bf16x2(float hi_e, float lo_e) {
    uint32_t r;
    asm("cvt.rn.bf16x2.f32 %0, %1, %2;" : "=r"(r) : "f"(hi_e), "f"(lo_e));
    return r;
}

// split 8 consecutive f32 -> hi (truncated bf16 x4 regs) + lo (residual bf16)
__device__ __forceinline__ void split8(const float4 v0, const float4 v1,
                                       uint4& hi, uint4& lo) {
    uint32_t u0=__float_as_uint(v0.x), u1=__float_as_uint(v0.y);
    uint32_t u2=__float_as_uint(v0.z), u3=__float_as_uint(v0.w);
    uint32_t u4=__float_as_uint(v1.x), u5=__float_as_uint(v1.y);
    uint32_t u6=__float_as_uint(v1.z), u7=__float_as_uint(v1.w);
    hi.x=(u0>>16)|(u1&0xFFFF0000u); hi.y=(u2>>16)|(u3&0xFFFF0000u);
    hi.z=(u4>>16)|(u5&0xFFFF0000u); hi.w=(u6>>16)|(u7&0xFFFF0000u);
    lo.x=bf16x2(v0.y-__uint_as_float(u1&0xFFFF0000u), v0.x-__uint_as_float(u0&0xFFFF0000u));
    lo.y=bf16x2(v0.w-__uint_as_float(u3&0xFFFF0000u), v0.z-__uint_as_float(u2&0xFFFF0000u));
    lo.z=bf16x2(v1.y-__uint_as_float(u5&0xFFFF0000u), v1.x-__uint_as_float(u4&0xFFFF0000u));
    lo.w=bf16x2(v1.w-__uint_as_float(u7&0xFFFF0000u), v1.z-__uint_as_float(u6&0xFFFF0000u));
}

// ---- prep: W [E][K][N] f32 -> g_Wh/g_Wl [E][N][K] bf16 (smem-tiled transpose) ----
__global__ void prep_W(const float* __restrict__ W) {
    __shared__ float tile[64][65];
    const int b  = blockIdx.x;          // 64 blocks: e (16) x k-seg (4)
    const int e  = b >> 2;
    const int k0 = (b & 3) * 64;
    const int t  = threadIdx.x;
    #pragma unroll
    for (int i = 0; i < 16; i++) {
        int idx = i * 256 + t;
        int kk = idx >> 6, nn = idx & 63;
        tile[kk][nn] = W[((size_t)e * DIM + k0 + kk) * PP + nn];
    }
    __syncthreads();
    #pragma unroll
    for (int i = 0; i < 16; i++) {
        int idx = i * 256 + t;
        int nn = idx >> 6, kk = idx & 63;
        float w = tile[kk][nn];
        uint32_t u = __float_as_uint(w);
        float hif = __uint_as_float(u & 0xFFFF0000u);
        size_t o = ((size_t)e * PP + nn) * DIM + k0 + kk;
        g_Wh[o] = __ushort_as_bfloat16((unsigned short)(u >> 16));
        g_Wl[o] = __float2bfloat16(w - hif);
    }
}

extern __shared__ char smem_raw[];

__global__ __launch_bounds__(NTHREADS, 2)
void moe_mma_kernel(const float* __restrict__ x,
                    const float* __restrict__ bias,
                    const int*   __restrict__ bidx,
                    float*       __restrict__ out,
                    int n_tokens)
{
    __shared__ int s_cnt;
    char* smem = smem_raw;
    const uint32_t sb = smem_u32(smem);
    int* s_rows = (int*)(smem + SM_ROWS);

    const int tid  = threadIdx.x;
    const int wid  = tid >> 5;
    const int lane = tid & 31;
    const int e    = blockIdx.y;
    const int base = blockIdx.x * TCHUNK;

    if (tid == 0) s_cnt = 0;
    __syncthreads();

    // ---- select tokens for expert e ----
    int lim = n_tokens - base;
    if (lim > TCHUNK) lim = TCHUNK;
    for (int i = tid; i < lim; i += NTHREADS) {
        if (bidx[base + i] == e) {
            int pos = atomicAdd(&s_cnt, 1);
            s_rows[pos] = base + i;
        }
    }
    __syncthreads();
    const int cnt = s_cnt;
    if (cnt == 0) return;

    // warp tiling: 2m x 4n warps, warp tile 32m x 16n
    const int wm = wid >> 2, wn = wid & 3;
    const int m_base = wm * 32, n_base = wn * 16;

    // A-frag lane geometry (matches validated R7 mapping)
    const uint32_t rowA0 = (uint32_t)(m_base + (lane & 7) + ((lane >> 3) & 1) * 8);
    const int      aKof  = (lane >> 4) * 8;

    // B-frag gmem bases: lane owns n = n_base + nj*8 + (lane>>2), k-pair at (lane&3)*2
    const size_t boff = ((size_t)e * PP + n_base + (lane >> 2)) * DIM + (lane & 3) * 2;
    const __nv_bfloat16* Bh = g_Wh + boff;
    const __nv_bfloat16* Bl = g_Wl + boff;

    // bias per lane per n-frag
    float2 bc[2];
    #pragma unroll
    for (int nj = 0; nj < 2; nj++)
        bc[nj] = *(const float2*)(bias + e * PP + n_base + nj * 8 + (lane & 3) * 2);

    // A staging map: 4 threads per row, 64-float k-segments
    const int st_r  = tid >> 2;
    const int st_ks = (tid & 3) * 64;

    for (int m0 = 0; m0 < cnt; m0 += MT) {
        int mcount = cnt - m0;
        if (mcount > MT) mcount = MT;

        __syncthreads();   // prior tile's ldmatrix readers done

        // ---- stage A hi/lo (gather + split) ----
        if (st_r < mcount) {
            const float* xr = x + (size_t)s_rows[m0 + st_r] * DIM + st_ks;
            #pragma unroll
            for (int c = 0; c < 8; c++) {
                int kb = c * 8;
                float4 v0 = *(const float4*)(xr + kb);
                float4 v1 = *(const float4*)(xr + kb + 4);
                uint4 hi, lo;
                split8(v0, v1, hi, lo);
                uint32_t so = tile_off((uint32_t)st_r, (uint32_t)(st_ks + kb));
                *(uint4*)(smem + SM_AH + so) = hi;
                *(uint4*)(smem + SM_AL + so) = lo;
            }
        }

        // B frag prologue (independent of smem) overlaps the staging barrier
        uint32_t bh[2][2][2], bl[2][2][2];   // [buf][nj][khalf]
        #pragma unroll
        for (int nj = 0; nj < 2; nj++) {
            bh[0][nj][0] = *(const uint32_t*)(Bh + nj * 8 * DIM);
            bh[0][nj][1] = *(const uint32_t*)(Bh + nj * 8 * DIM + 8);
            bl[0][nj][0] = *(const uint32_t*)(Bl + nj * 8 * DIM);
            bl[0][nj][1] = *(const uint32_t*)(Bl + nj * 8 * DIM + 8);
        }
        __syncthreads();

        float acc[2][2][4];
        #pragma unroll
        for (int i = 0; i < 2; i++)
            #pragma unroll
            for (int j = 0; j < 2; j++)
                #pragma unroll
                for (int q = 0; q < 4; q++) acc[i][j][q] = 0.f;

        #pragma unroll
        for (int ks = 0; ks < 16; ks++) {
            const int cur = ks & 1, nxt = cur ^ 1;
            if (ks < 15) {   // prefetch B frags for ks+1
                const int ko = (ks + 1) * 16;
                #pragma unroll
                for (int nj = 0; nj < 2; nj++) {
                    bh[nxt][nj][0] = *(const uint32_t*)(Bh + nj * 8 * DIM + ko);
                    bh[nxt][nj][1] = *(const uint32_t*)(Bh + nj * 8 * DIM + ko + 8);
                    bl[nxt][nj][0] = *(const uint32_t*)(Bl + nj * 8 * DIM + ko);
                    bl[nxt][nj][1] = *(const uint32_t*)(Bl + nj * 8 * DIM + ko + 8);
                }
            }

            const uint32_t kk = (uint32_t)(ks * 16);
            uint32_t aoff = tile_off(rowA0, kk + (uint32_t)aKof);
            uint32_t AH0[4], AH1[4], AL0[4], AL1[4];
            ldmx4(AH0, sb + SM_AH + aoff);
            ldmx4(AH1, sb + SM_AH + aoff + 16 * 512);
            ldmx4(AL0, sb + SM_AL + aoff);
            ldmx4(AL1, sb + SM_AL + aoff + 16 * 512);

            #pragma unroll
            for (int nj = 0; nj < 2; nj++) {
                mma16816(acc[0][nj], AH0, bh[cur][nj][0], bh[cur][nj][1]);
                mma16816(acc[1][nj], AH1, bh[cur][nj][0], bh[cur][nj][1]);
                mma16816(acc[0][nj], AL0, bh[cur][nj][0], bh[cur][nj][1]);
                mma16816(acc[1][nj], AL1, bh[cur][nj][0], bh[cur][nj][1]);
                mma16816(acc[0][nj], AH0, bl[cur][nj][0], bl[cur][nj][1]);
                mma16816(acc[1][nj], AH1, bl[cur][nj][0], bl[cur][nj][1]);
            }
        }

        // ---- epilogue: bias + scattered stores ----
        #pragma unroll
        for (int mi = 0; mi < 2; mi++) {
            int r0 = m_base + mi * 16 + (lane >> 2);
            int r1 = r0 + 8;
            #pragma unroll
            for (int nj = 0; nj < 2; nj++) {
                int c = n_base + nj * 8 + (lane & 3) * 2;
                if (r0 < mcount) {
                    float2 v = make_float2(acc[mi][nj][0] + bc[nj].x,
                                           acc[mi][nj][1] + bc[nj].y);
                    *(float2*)(out + (size_t)s_rows[m0 + r0] * PP + c) = v;
                }
                if (r1 < mcount) {
                    float2 v = make_float2(acc[mi][nj][2] + bc[nj].x,
                                           acc[mi][nj][3] + bc[nj].y);
                    *(float2*)(out + (size_t)s_rows[m0 + r1] * PP + c) = v;
                }
            }
        }
    }
}

extern "C" void kernel_launch(void* const* d_in, const int* in_sizes, int n_in,
                              void* d_out, int out_size) {
    const float* x    = (const float*)d_in[0];
    const float* W    = (const float*)d_in[1];
    const float* bias = (const float*)d_in[2];
    const int*   idx  = (const int*)d_in[3];
    float*       out  = (float*)d_out;

    const int n_tokens = in_sizes[3];

    prep_W<<<64, 256>>>(W);

    cudaFuncSetAttribute(moe_mma_kernel,
                         cudaFuncAttributeMaxDynamicSharedMemorySize, SMEM_DYN);

    dim3 grid((n_tokens + TCHUNK - 1) / TCHUNK, NEXP);
    moe_mma_kernel<<<grid, NTHREADS, SMEM_DYN>>>(x, bias, idx, out, n_tokens);
}

// round 10
// speedup vs baseline: 2.0950x; 1.3130x over previous
#include <cuda_runtime.h>
#include <cuda_bf16.h>
#include <cstdint>

#define NEXP     16
#define DIM      256     // K
#define PP       64      // N
#define TCHUNK   2048
#define MT       32      // M tile rows
#define NTHREADS 256

// smem layout (bytes): B hi/lo [64][256]bf16 swizzled, A hi/lo [32][256], rows
#define SM_BH    0
#define SM_BL    32768
#define SM_AH    65536
#define SM_AL    81920
#define SM_ROWS  98304
#define SMEM_DYN 106496

// prepped weights: [E][N][K] bf16, hi = truncated top-16, lo = rounded residual
__device__ __nv_bfloat16 g_Wh[NEXP * PP * DIM];
__device__ __nv_bfloat16 g_Wl[NEXP * PP * DIM];

__device__ __forceinline__ uint32_t smem_u32(const void* p) {
    uint32_t a;
    asm("{ .reg .u64 t; cvta.to.shared.u64 t, %1; cvt.u32.u64 %0, t; }" : "=r"(a) : "l"(p));
    return a;
}

// Swizzled tile: row-major [r][k] bf16, row stride 512B; 16B chunks XOR-permuted
// within each 128B group -> ldmatrix (8 rows, same k-chunk) conflict-free.
__device__ __forceinline__ uint32_t tile_off(uint32_t r, uint32_t k) {
    uint32_t ch  = k >> 3;
    uint32_t chs = (ch & 24u) | ((ch ^ r) & 7u);
    return r * 512u + chs * 16u + (k & 7u) * 2u;
}

__device__ __forceinline__ void ldmx4(uint32_t (&r)[4], uint32_t a) {
    asm volatile("ldmatrix.sync.aligned.m8n8.x4.shared.b16 {%0,%1,%2,%3}, [%4];"
                 : "=r"(r[0]), "=r"(r[1]), "=r"(r[2]), "=r"(r[3]) : "r"(a));
}

__device__ __forceinline__ void mma16816(float (&d)[4], const uint32_t (&a)[4],
                                         uint32_t b0, uint32_t b1) {
    asm volatile("mma.sync.aligned.m16n8k16.row.col.f32.bf16.bf16.f32 "
                 "{%0,%1,%2,%3}, {%4,%5,%6,%7}, {%8,%9}, {%0,%1,%2,%3};"
                 : "+f"(d[0]), "+f"(d[1]), "+f"(d[2]), "+f"(d[3])
                 : "r"(a[0]), "r"(a[1]), "r"(a[2]), "r"(a[3]), "r"(b0), "r"(b1));
}

__device__ __forceinline__ uint32_t bf16x2(float hi_e, float lo_e) {
    uint32_t r;
    asm("cvt.rn.bf16x2.f32 %0, %1, %2;" : "=r"(r) : "f"(hi_e), "f"(lo_e));
    return r;
}

// split 8 consecutive f32 -> hi (truncated bf16) + lo (rounded residual bf16)
__device__ __forceinline__ void split8(const float4 v0, const float4 v1,
                                       uint4& hi, uint4& lo) {
    uint32_t u0=__float_as_uint(v0.x), u1=__float_as_uint(v0.y);
    uint32_t u2=__float_as_uint(v0.z), u3=__float_as_uint(v0.w);
    uint32_t u4=__float_as_uint(v1.x), u5=__float_as_uint(v1.y);
    uint32_t u6=__float_as_uint(v1.z), u7=__float_as_uint(v1.w);
    hi.x=(u0>>16)|(u1&0xFFFF0000u); hi.y=(u2>>16)|(u3&0xFFFF0000u);
    hi.z=(u4>>16)|(u5&0xFFFF0000u); hi.w=(u6>>16)|(u7&0xFFFF0000u);
    lo.x=bf16x2(v0.y-__uint_as_float(u1&0xFFFF0000u), v0.x-__uint_as_float(u0&0xFFFF0000u));
    lo.y=bf16x2(v0.w-__uint_as_float(u3&0xFFFF0000u), v0.z-__uint_as_float(u2&0xFFFF0000u));
    lo.z=bf16x2(v1.y-__uint_as_float(u5&0xFFFF0000u), v1.x-__uint_as_float(u4&0xFFFF0000u));
    lo.w=bf16x2(v1.w-__uint_as_float(u7&0xFFFF0000u), v1.z-__uint_as_float(u6&0xFFFF0000u));
}

// ---- prep: W [E][K][N] f32 -> g_Wh/g_Wl [E][N][K] bf16 (smem-tiled transpose) ----
__global__ void prep_W(const float* __restrict__ W) {
    __shared__ float tile[64][65];
    const int b  = blockIdx.x;          // 64 blocks: e (16) x k-seg (4)
    const int e  = b >> 2;
    const int k0 = (b & 3) * 64;
    const int t  = threadIdx.x;
    #pragma unroll
    for (int i = 0; i < 16; i++) {
        int idx = i * 256 + t;
        int kk = idx >> 6, nn = idx & 63;
        tile[kk][nn] = W[((size_t)e * DIM + k0 + kk) * PP + nn];
    }
    __syncthreads();
    #pragma unroll
    for (int i = 0; i < 16; i++) {
        int idx = i * 256 + t;
        int nn = idx >> 6, kk = idx & 63;
        float w = tile[kk][nn];
        uint32_t u = __float_as_uint(w);
        float hif = __uint_as_float(u & 0xFFFF0000u);
        size_t o = ((size_t)e * PP + nn) * DIM + k0 + kk;
        g_Wh[o] = __ushort_as_bfloat16((unsigned short)(u >> 16));
        g_Wl[o] = __float2bfloat16(w - hif);
    }
}

extern __shared__ char smem_raw[];

__global__ __launch_bounds__(NTHREADS, 2)
void moe_mma_kernel(const float* __restrict__ x,
                    const float* __restrict__ bias,
                    const int*   __restrict__ bidx,
                    float*       __restrict__ out,
                    int n_tokens)
{
    __shared__ int s_cnt;
    char* smem = smem_raw;
    const uint32_t sb = smem_u32(smem);
    int* s_rows = (int*)(smem + SM_ROWS);

    const int tid  = threadIdx.x;
    const int wid  = tid >> 5;
    const int lane = tid & 31;
    const int e    = blockIdx.y;
    const int base = blockIdx.x * TCHUNK;

    if (tid == 0) s_cnt = 0;
    __syncthreads();

    // ---- stage B = W[e] hi/lo into swizzled smem (independent of select) ----
    {
        const __nv_bfloat16* wh = g_Wh + (size_t)e * PP * DIM;
        const __nv_bfloat16* wl = g_Wl + (size_t)e * PP * DIM;
        #pragma unroll
        for (int p = 0; p < (PP * DIM / 8) / NTHREADS; p++) {   // 8 passes
            int i  = p * NTHREADS + tid;
            int n  = i >> 5;
            int k8 = (i & 31) * 8;
            uint32_t so = tile_off((uint32_t)n, (uint32_t)k8);
            *(uint4*)(smem + SM_BH + so) = *(const uint4*)(wh + (size_t)n * DIM + k8);
            *(uint4*)(smem + SM_BL + so) = *(const uint4*)(wl + (size_t)n * DIM + k8);
        }
    }

    // ---- select tokens for expert e ----
    int lim = n_tokens - base;
    if (lim > TCHUNK) lim = TCHUNK;
    for (int i = tid; i < lim; i += NTHREADS) {
        if (bidx[base + i] == e) {
            int pos = atomicAdd(&s_cnt, 1);
            s_rows[pos] = base + i;
        }
    }
    __syncthreads();
    const int cnt = s_cnt;
    if (cnt == 0) return;

    // warp tiling: 2m x 4n warps, warp tile 16m x 16n
    const int m_base = (wid >> 2) * 16;
    const int n_base = (wid & 3) * 16;

    // 4-group ldmatrix address pattern (validated R7 mapping):
    // lanes 0-7: rows +0..7 @k+0 | 8-15: rows +8..15 @k+0 | 16-23: +0..7 @k+8 | 24-31: +8..15 @k+8
    const uint32_t rgrp = (uint32_t)((lane & 7) + ((lane >> 3) & 1) * 8);
    const uint32_t kofs = (uint32_t)((lane >> 4) * 8);
    const uint32_t rowA = (uint32_t)m_base + rgrp;
    const uint32_t rowB = (uint32_t)n_base + rgrp;

    // bias per lane per n-frag
    float2 bc[2];
    #pragma unroll
    for (int nj = 0; nj < 2; nj++)
        bc[nj] = *(const float2*)(bias + e * PP + n_base + nj * 8 + (lane & 3) * 2);

    // A staging map: 8 threads per row, 32-float segments
    const int st_r  = tid >> 3;
    const int st_ks = (tid & 7) * 32;

    for (int m0 = 0; m0 < cnt; m0 += MT) {
        int mcount = cnt - m0;
        if (mcount > MT) mcount = MT;

        __syncthreads();   // prior tile's ldmatrix readers done

        // ---- stage A hi/lo (gather + split) ----
        if (st_r < mcount) {
            const float* xr = x + (size_t)s_rows[m0 + st_r] * DIM + st_ks;
            #pragma unroll
            for (int c = 0; c < 4; c++) {
                int kb = c * 8;
                float4 v0 = *(const float4*)(xr + kb);
                float4 v1 = *(const float4*)(xr + kb + 4);
                uint4 hi, lo;
                split8(v0, v1, hi, lo);
                uint32_t so = tile_off((uint32_t)st_r, (uint32_t)(st_ks + kb));
                *(uint4*)(smem + SM_AH + so) = hi;
                *(uint4*)(smem + SM_AL + so) = lo;
            }
        }
        __syncthreads();

        float acc[2][4];
        #pragma unroll
        for (int j = 0; j < 2; j++)
            #pragma unroll
            for (int q = 0; q < 4; q++) acc[j][q] = 0.f;

        #pragma unroll
        for (int ks = 0; ks < 16; ks++) {
            const uint32_t kk = (uint32_t)(ks * 16) + kofs;
            uint32_t aoff = tile_off(rowA, kk);
            uint32_t boff = tile_off(rowB, kk);

            uint32_t AH[4], AL[4], BH[4], BL[4];
            ldmx4(AH, sb + SM_AH + aoff);
            ldmx4(BH, sb + SM_BH + boff);
            ldmx4(AL, sb + SM_AL + aoff);
            ldmx4(BL, sb + SM_BL + boff);

            // BH[0],BH[2] = nj0 (k0,k8); BH[1],BH[3] = nj1
            mma16816(acc[0], AH, BH[0], BH[2]);
            mma16816(acc[1], AH, BH[1], BH[3]);
            mma16816(acc[0], AL, BH[0], BH[2]);
            mma16816(acc[1], AL, BH[1], BH[3]);
            mma16816(acc[0], AH, BL[0], BL[2]);
            mma16816(acc[1], AH, BL[1], BL[3]);
        }

        // ---- epilogue: bias + scattered stores ----
        {
            int r0 = m_base + (lane >> 2);
            int r1 = r0 + 8;
            #pragma unroll
            for (int nj = 0; nj < 2; nj++) {
                int c = n_base + nj * 8 + (lane & 3) * 2;
                if (r0 < mcount) {
                    float2 v = make_float2(acc[nj][0] + bc[nj].x,
                                           acc[nj][1] + bc[nj].y);
                    *(float2*)(out + (size_t)s_rows[m0 + r0] * PP + c) = v;
                }
                if (r1 < mcount) {
                    float2 v = make_float2(acc[nj][2] + bc[nj].x,
                                           acc[nj][3] + bc[nj].y);
                    *(float2*)(out + (size_t)s_rows[m0 + r1] * PP + c) = v;
                }
            }
        }
    }
}

extern "C" void kernel_launch(void* const* d_in, const int* in_sizes, int n_in,
                              void* d_out, int out_size) {
    const float* x    = (const float*)d_in[0];
    const float* W    = (const float*)d_in[1];
    const float* bias = (const float*)d_in[2];
    const int*   idx  = (const int*)d_in[3];
    float*       out  = (float*)d_out;

    const int n_tokens = in_sizes[3];

    prep_W<<<64, 256>>>(W);

    cudaFuncSetAttribute(moe_mma_kernel,
                         cudaFuncAttributeMaxDynamicSharedMemorySize, SMEM_DYN);

    dim3 grid((n_tokens + TCHUNK - 1) / TCHUNK, NEXP);
    moe_mma_kernel<<<grid, NTHREADS, SMEM_DYN>>>(x, bias, idx, out, n_tokens);
}